// round 1
// baseline (speedup 1.0000x reference)
#include <cuda_runtime.h>

#define N 4096
#define NN (N * N)
#define NITERS 300

// 64MB cost matrix, stored first as C, then scaled in place to B = C * log2(e)/eps
__device__ float  d_B[NN];
__device__ float  d_F[N];
__device__ float  d_G[N];
__device__ double d_csum;   // sum of C for mean/eps
__device__ double d_emd;    // final accumulator
__device__ float  d_k;      // log2(e)/eps

__device__ __forceinline__ float ex2f(float x) {
    float y;
    asm("ex2.approx.ftz.f32 %0, %1;" : "=f"(y) : "f"(x));
    return y;
}

// ---------------------------------------------------------------- init
__global__ void k_init() {
    d_csum = 0.0;
    d_emd  = 0.0;
}

// ---------------------------------------------------------------- build C + partial mean
// one block per row i, 256 threads over columns
__global__ void k_build(const float* __restrict__ x, const float* __restrict__ y) {
    __shared__ float sred[8];
    int i = blockIdx.x;
    float xi0 = x[3 * i + 0], xi1 = x[3 * i + 1], xi2 = x[3 * i + 2];
    float x2 = xi0 * xi0 + xi1 * xi1 + xi2 * xi2;

    float acc = 0.0f;
    for (int j = threadIdx.x; j < N; j += 256) {
        float y0 = y[3 * j + 0], y1 = y[3 * j + 1], y2 = y[3 * j + 2];
        float yy  = y0 * y0 + y1 * y1 + y2 * y2;
        float dot = xi0 * y0 + xi1 * y1 + xi2 * y2;
        float d2  = x2 + yy - 2.0f * dot;
        float c   = sqrtf(fmaxf(d2, 0.0f) + 1e-12f);
        d_B[(size_t)i * N + j] = c;
        acc += c;
    }
    // block reduce acc
    for (int o = 16; o; o >>= 1) acc += __shfl_down_sync(0xffffffffu, acc, o);
    if ((threadIdx.x & 31) == 0) sred[threadIdx.x >> 5] = acc;
    __syncthreads();
    if (threadIdx.x < 8) {
        acc = sred[threadIdx.x];
        for (int o = 4; o; o >>= 1) acc += __shfl_down_sync(0xffu, acc, o);
        if (threadIdx.x == 0) atomicAdd(&d_csum, (double)acc);
    }
}

// ---------------------------------------------------------------- eps
__global__ void k_eps() {
    double mean = d_csum / (double)NN;
    double eps  = 0.02 * mean;
    d_k = (float)(1.4426950408889634 / eps);  // log2(e)/eps
}

// ---------------------------------------------------------------- scale B in place, zero F/G
__global__ void k_scale() {
    int idx = blockIdx.x * blockDim.x + threadIdx.x;  // over NN/4 float4s
    float k = d_k;
    float4* B4 = (float4*)d_B;
    if (idx < NN / 4) {
        float4 v = B4[idx];
        v.x *= k; v.y *= k; v.z *= k; v.w *= k;
        B4[idx] = v;
    }
    if (idx < N) { d_F[idx] = 0.0f; d_G[idx] = 0.0f; }
}

// ---------------------------------------------------------------- f pass
// F_new_i = F_i - log2( sum_j 2^(G_j + F_i - B_ij - 12) )
// one block per row, 256 threads, G staged in smem, float4 streaming reads of B
__global__ void k_f() {
    __shared__ float sG[N];
    __shared__ float sred[8];
    int i = blockIdx.x;
    for (int j = threadIdx.x; j < N; j += 256) sG[j] = d_G[j];
    __syncthreads();

    float Fi = d_F[i];
    float c  = Fi - 12.0f;  // -log2(n)
    const float4* Br = (const float4*)(d_B + (size_t)i * N);
    const float4* G4 = (const float4*)sG;

    float s0 = 0.f, s1 = 0.f, s2 = 0.f, s3 = 0.f;
#pragma unroll
    for (int t = threadIdx.x; t < N / 4; t += 256) {
        float4 b = Br[t];
        float4 g = G4[t];
        s0 += ex2f(g.x - b.x + c);
        s1 += ex2f(g.y - b.y + c);
        s2 += ex2f(g.z - b.z + c);
        s3 += ex2f(g.w - b.w + c);
    }
    float s = (s0 + s1) + (s2 + s3);
    for (int o = 16; o; o >>= 1) s += __shfl_down_sync(0xffffffffu, s, o);
    if ((threadIdx.x & 31) == 0) sred[threadIdx.x >> 5] = s;
    __syncthreads();
    if (threadIdx.x < 8) {
        s = sred[threadIdx.x];
        for (int o = 4; o; o >>= 1) s += __shfl_down_sync(0xffu, s, o);
        if (threadIdx.x == 0) d_F[i] = Fi - log2f(s);
    }
}

// ---------------------------------------------------------------- g pass
// G_new_j = G_j - log2( sum_i 2^(F_i + G_j - B_ij - 12) )
// 256 blocks x 16 cols; 256 threads = 16 cols (tx) x 16 row-lanes (ty);
// coalesced row-major reads of B, F staged in smem
__global__ void k_g() {
    __shared__ float sF[N];
    __shared__ float sr[16][17];
    int tid = threadIdx.x;
    for (int i = tid; i < N; i += 256) sF[i] = d_F[i];
    __syncthreads();

    int tx = tid & 15, ty = tid >> 4;
    int j  = blockIdx.x * 16 + tx;
    float Gj = d_G[j];
    float c  = Gj - 12.0f;

    float s0 = 0.f, s1 = 0.f;
#pragma unroll 8
    for (int i = ty; i < N; i += 32) {
        s0 += ex2f(sF[i]      + c - d_B[(size_t)i        * N + j]);
        s1 += ex2f(sF[i + 16] + c - d_B[(size_t)(i + 16) * N + j]);
    }
    sr[ty][tx] = s0 + s1;
    __syncthreads();
    for (int o = 8; o; o >>= 1) {
        if (ty < o) sr[ty][tx] += sr[ty + o][tx];
        __syncthreads();
    }
    if (ty == 0) d_G[j] = Gj - log2f(sr[0][tx]);
}

// ---------------------------------------------------------------- final: sum P*C
// P_ij = 2^(F_i + G_j - B_ij - 24),  C_ij = B_ij / k
// accumulate sum 2^(...)*B, divide by k at write-out
__global__ void k_final() {
    __shared__ float sG[N];
    __shared__ float sred[8];
    int i = blockIdx.x;
    for (int j = threadIdx.x; j < N; j += 256) sG[j] = d_G[j];
    __syncthreads();

    float c = d_F[i] - 24.0f;  // -2*log2(n)
    const float4* Br = (const float4*)(d_B + (size_t)i * N);
    const float4* G4 = (const float4*)sG;

    float s0 = 0.f, s1 = 0.f, s2 = 0.f, s3 = 0.f;
#pragma unroll
    for (int t = threadIdx.x; t < N / 4; t += 256) {
        float4 b = Br[t];
        float4 g = G4[t];
        s0 += ex2f(g.x - b.x + c) * b.x;
        s1 += ex2f(g.y - b.y + c) * b.y;
        s2 += ex2f(g.z - b.z + c) * b.z;
        s3 += ex2f(g.w - b.w + c) * b.w;
    }
    float s = (s0 + s1) + (s2 + s3);
    for (int o = 16; o; o >>= 1) s += __shfl_down_sync(0xffffffffu, s, o);
    if ((threadIdx.x & 31) == 0) sred[threadIdx.x >> 5] = s;
    __syncthreads();
    if (threadIdx.x < 8) {
        s = sred[threadIdx.x];
        for (int o = 4; o; o >>= 1) s += __shfl_down_sync(0xffu, s, o);
        if (threadIdx.x == 0) atomicAdd(&d_emd, (double)s);
    }
}

// ---------------------------------------------------------------- write scalar
__global__ void k_write(float* __restrict__ out) {
    out[0] = (float)(d_emd / (double)d_k);
}

// ---------------------------------------------------------------- launch
extern "C" void kernel_launch(void* const* d_in, const int* in_sizes, int n_in,
                              void* d_out, int out_size) {
    const float* x = (const float*)d_in[0];
    const float* y = (const float*)d_in[1];
    float* out = (float*)d_out;

    k_init<<<1, 1>>>();
    k_build<<<N, 256>>>(x, y);
    k_eps<<<1, 1>>>();
    k_scale<<<(NN / 4 + 255) / 256, 256>>>();

    for (int it = 0; it < NITERS; it++) {
        k_f<<<N, 256>>>();
        k_g<<<N / 16, 256>>>();
    }

    k_final<<<N, 256>>>();
    k_write<<<1, 1>>>(out);
}

// round 2
// speedup vs baseline: 1.4802x; 1.4802x over previous
#include <cuda_runtime.h>

#define N 4096
#define NN (N * N)
#define NITERS 300
#define NBLK 148
#define TPB 1024

// B holds the RAW cost matrix C (never scaled); k = log2(e)/eps folded into the loop.
__device__ float  d_B[NN];
__device__ float  d_F[N];
__device__ float  d_G[N];
__device__ double d_csum;
__device__ double d_emd;
__device__ float  d_k;
__device__ unsigned int          g_bar;
__device__ volatile unsigned int g_epoch;

__device__ __forceinline__ float ex2f(float x) {
    float y;
    asm("ex2.approx.ftz.f32 %0, %1;" : "=f"(y) : "f"(x));
    return y;
}

// ---------------------------------------------------------------- init
__global__ void k_init() {
    d_csum  = 0.0;
    d_emd   = 0.0;
    g_bar   = 0u;
    g_epoch = 0u;
}

// ---------------------------------------------------------------- build C + partial sum; zero F/G
__global__ void k_build(const float* __restrict__ x, const float* __restrict__ y) {
    __shared__ float sred[8];
    int i = blockIdx.x;
    float xi0 = x[3 * i + 0], xi1 = x[3 * i + 1], xi2 = x[3 * i + 2];
    float x2 = xi0 * xi0 + xi1 * xi1 + xi2 * xi2;

    float acc = 0.0f;
    for (int j = threadIdx.x; j < N; j += 256) {
        float y0 = y[3 * j + 0], y1 = y[3 * j + 1], y2 = y[3 * j + 2];
        float yy  = y0 * y0 + y1 * y1 + y2 * y2;
        float dot = xi0 * y0 + xi1 * y1 + xi2 * y2;
        float d2  = x2 + yy - 2.0f * dot;
        float c   = sqrtf(fmaxf(d2, 0.0f) + 1e-12f);
        d_B[(size_t)i * N + j] = c;
        acc += c;
    }
    for (int o = 16; o; o >>= 1) acc += __shfl_down_sync(0xffffffffu, acc, o);
    if ((threadIdx.x & 31) == 0) sred[threadIdx.x >> 5] = acc;
    __syncthreads();
    if (threadIdx.x < 8) {
        acc = sred[threadIdx.x];
        for (int o = 4; o; o >>= 1) acc += __shfl_down_sync(0xffu, acc, o);
        if (threadIdx.x == 0) atomicAdd(&d_csum, (double)acc);
    }
    if (threadIdx.x == 0) { d_F[i] = 0.0f; d_G[i] = 0.0f; }
}

// ---------------------------------------------------------------- eps -> k
__global__ void k_eps() {
    double mean = d_csum / (double)NN;
    double eps  = 0.02 * mean;
    d_k = (float)(1.4426950408889634 / eps);
}

// ---------------------------------------------------------------- grid barrier (all NBLK blocks co-resident)
__device__ __forceinline__ void gsync(unsigned int& ep) {
    __threadfence();
    __syncthreads();
    if (threadIdx.x == 0) {
        unsigned int t = atomicAdd(&g_bar, 1u);
        if (t == NBLK - 1) {
            g_bar = 0u;
            __threadfence();
            g_epoch = ep + 1u;
        } else {
            while (g_epoch == ep) { }
            __threadfence();
        }
    }
    ep++;
    __syncthreads();
}

// ---------------------------------------------------------------- persistent Sinkhorn loop + final P*C
__global__ void __launch_bounds__(TPB, 1) k_persist(float* __restrict__ out) {
    __shared__ float sV[N];          // staged G (f pass) or F (g pass)
    __shared__ float sred[8][4];     // f-pass per-row reduce
    __shared__ float sr[32][33];     // g-pass 32x32 transpose-reduce / final reduce
    const int tid = threadIdx.x;
    const int bid = blockIdx.x;
    const float k = d_k;
    unsigned int ep = 0u;

    const int grp = tid >> 7;        // 0..7   : row group within block
    const int ln  = tid & 127;       // 0..127 : lane within row group
    const int tx  = tid & 31;        // g-pass : column lane
    const int ty  = tid >> 5;        // g-pass : row lane / warp id

    for (int it = 0; it < NITERS; it++) {
        // ---------------- f pass: F_i <- F_i - log2(sum_j 2^(G_j - k*B_ij + F_i - 12))
        for (int j = tid; j < N; j += TPB) sV[j] = d_G[j];
        __syncthreads();

        for (int base = bid * 8; base < N; base += NBLK * 8) {
            int i = base + grp;
            float Fi = d_F[i];
            float c  = Fi - 12.0f;
            const float4* Br = (const float4*)(d_B + (size_t)i * N);
            const float4* V4 = (const float4*)sV;
            float s0 = 0.f, s1 = 0.f, s2 = 0.f, s3 = 0.f;
#pragma unroll 4
            for (int t = ln; t < N / 4; t += 128) {
                float4 b = Br[t];
                float4 g = V4[t];
                s0 += ex2f(fmaf(-k, b.x, g.x + c));
                s1 += ex2f(fmaf(-k, b.y, g.y + c));
                s2 += ex2f(fmaf(-k, b.z, g.z + c));
                s3 += ex2f(fmaf(-k, b.w, g.w + c));
            }
            float s = (s0 + s1) + (s2 + s3);
            for (int o = 16; o; o >>= 1) s += __shfl_down_sync(0xffffffffu, s, o);
            if ((ln & 31) == 0) sred[grp][ln >> 5] = s;
            __syncthreads();
            if (ln == 0) {
                s = (sred[grp][0] + sred[grp][1]) + (sred[grp][2] + sred[grp][3]);
                d_F[i] = Fi - log2f(s);
            }
            __syncthreads();
        }
        gsync(ep);

        // ---------------- g pass: G_j <- G_j - log2(sum_i 2^(F_i - k*B_ij + G_j - 12))
        for (int i = tid; i < N; i += TPB) sV[i] = d_F[i];
        __syncthreads();

        for (int j0 = bid * 32; j0 < N; j0 += NBLK * 32) {
            int j = j0 + tx;
            float Gj = d_G[j];
            float c  = Gj - 12.0f;
            const float* Bc = d_B + j;
            float s0 = 0.f, s1 = 0.f, s2 = 0.f, s3 = 0.f;
#pragma unroll 4
            for (int i = ty; i < N; i += 128) {
                s0 += ex2f(fmaf(-k, Bc[(size_t)i * N],        sV[i]      + c));
                s1 += ex2f(fmaf(-k, Bc[(size_t)(i + 32) * N], sV[i + 32] + c));
                s2 += ex2f(fmaf(-k, Bc[(size_t)(i + 64) * N], sV[i + 64] + c));
                s3 += ex2f(fmaf(-k, Bc[(size_t)(i + 96) * N], sV[i + 96] + c));
            }
            sr[ty][tx] = (s0 + s1) + (s2 + s3);
            __syncthreads();
            // warp ty reduces column ty of sr
            float v = sr[tx][ty];
            for (int o = 16; o; o >>= 1) v += __shfl_down_sync(0xffffffffu, v, o);
            if (tx == 0) {
                int jj = j0 + ty;
                float G0 = d_G[jj];
                d_G[jj] = G0 - log2f(v);
            }
            __syncthreads();
        }
        gsync(ep);
    }

    // ---------------- final: sum_ij P_ij * C_ij,  P = 2^(F_i + G_j - k*B_ij - 24), C = B
    for (int j = tid; j < N; j += TPB) sV[j] = d_G[j];
    __syncthreads();

    float a0 = 0.f, a1 = 0.f, a2 = 0.f, a3 = 0.f;
    for (int base = bid * 8; base < N; base += NBLK * 8) {
        int i = base + grp;
        float c = d_F[i] - 24.0f;
        const float4* Br = (const float4*)(d_B + (size_t)i * N);
        const float4* V4 = (const float4*)sV;
#pragma unroll 4
        for (int t = ln; t < N / 4; t += 128) {
            float4 b = Br[t];
            float4 g = V4[t];
            a0 += ex2f(fmaf(-k, b.x, g.x + c)) * b.x;
            a1 += ex2f(fmaf(-k, b.y, g.y + c)) * b.y;
            a2 += ex2f(fmaf(-k, b.z, g.z + c)) * b.z;
            a3 += ex2f(fmaf(-k, b.w, g.w + c)) * b.w;
        }
    }
    float s = (a0 + a1) + (a2 + a3);
    for (int o = 16; o; o >>= 1) s += __shfl_down_sync(0xffffffffu, s, o);
    __syncthreads();                       // sr reuse safe
    if ((tid & 31) == 0) sr[0][tid >> 5] = s;
    __syncthreads();
    if (tid < 32) {
        s = sr[0][tid];
        for (int o = 16; o; o >>= 1) s += __shfl_down_sync(0xffffffffu, s, o);
        if (tid == 0) atomicAdd(&d_emd, (double)s);
    }
    gsync(ep);
    if (bid == 0 && tid == 0) out[0] = (float)d_emd;
}

// ---------------------------------------------------------------- launch
extern "C" void kernel_launch(void* const* d_in, const int* in_sizes, int n_in,
                              void* d_out, int out_size) {
    const float* x = (const float*)d_in[0];
    const float* y = (const float*)d_in[1];
    float* out = (float*)d_out;

    k_init<<<1, 1>>>();
    k_build<<<N, 256>>>(x, y);
    k_eps<<<1, 1>>>();
    k_persist<<<NBLK, TPB>>>(out);
}

// round 3
// speedup vs baseline: 1.7645x; 1.1920x over previous
#include <cuda_runtime.h>

#define N 4096
#define NN (N * N)
#define NITERS 300
#define NBLK 128
#define TPB 1024

// B holds the RAW cost matrix C; k = log2(e)/eps folded into the inner loop.
__device__ float  d_B[NN];
__device__ float  d_F[N];
__device__ float  d_G[N];
__device__ double d_csum;
__device__ double d_emd;
__device__ float  d_k;
__device__ unsigned int g_bar;
__device__ unsigned int g_epoch;

__device__ __forceinline__ float ex2f(float x) {
    float y;
    asm("ex2.approx.ftz.f32 %0, %1;" : "=f"(y) : "f"(x));
    return y;
}

// L2-only load (no L1 allocation) -> no stale-L1 hazard for cross-SM data
__device__ __forceinline__ float ldcg(const float* p) { return __ldcg(p); }

// ---------------------------------------------------------------- init
__global__ void k_init() {
    d_csum  = 0.0;
    d_emd   = 0.0;
    g_bar   = 0u;
    g_epoch = 0u;
}

// ---------------------------------------------------------------- build C + partial sum; zero F/G
__global__ void k_build(const float* __restrict__ x, const float* __restrict__ y) {
    __shared__ float sred[8];
    int i = blockIdx.x;
    float xi0 = x[3 * i + 0], xi1 = x[3 * i + 1], xi2 = x[3 * i + 2];
    float x2 = xi0 * xi0 + xi1 * xi1 + xi2 * xi2;

    float acc = 0.0f;
    for (int j = threadIdx.x; j < N; j += 256) {
        float y0 = y[3 * j + 0], y1 = y[3 * j + 1], y2 = y[3 * j + 2];
        float yy  = y0 * y0 + y1 * y1 + y2 * y2;
        float dot = xi0 * y0 + xi1 * y1 + xi2 * y2;
        float d2  = x2 + yy - 2.0f * dot;
        float c   = sqrtf(fmaxf(d2, 0.0f) + 1e-12f);
        d_B[(size_t)i * N + j] = c;
        acc += c;
    }
    for (int o = 16; o; o >>= 1) acc += __shfl_down_sync(0xffffffffu, acc, o);
    if ((threadIdx.x & 31) == 0) sred[threadIdx.x >> 5] = acc;
    __syncthreads();
    if (threadIdx.x < 8) {
        acc = sred[threadIdx.x];
        for (int o = 4; o; o >>= 1) acc += __shfl_down_sync(0xffu, acc, o);
        if (threadIdx.x == 0) atomicAdd(&d_csum, (double)acc);
    }
    if (threadIdx.x == 0) { d_F[i] = 0.0f; d_G[i] = 0.0f; }
}

// ---------------------------------------------------------------- eps -> k
__global__ void k_eps() {
    double mean = d_csum / (double)NN;
    double eps  = 0.02 * mean;
    d_k = (float)(1.4426950408889634 / eps);
}

// ---------------------------------------------------------------- grid barrier, no membar/IVALL
__device__ __forceinline__ void gsync(unsigned int& ep) {
    __syncthreads();
    if (threadIdx.x == 0) {
        unsigned int t;
        asm volatile("atom.add.release.gpu.u32 %0, [%1], 1;"
                     : "=r"(t) : "l"(&g_bar) : "memory");
        if (t == NBLK - 1) {
            g_bar = 0u;
            asm volatile("st.release.gpu.u32 [%0], %1;"
                         :: "l"(&g_epoch), "r"(ep + 1u) : "memory");
        } else {
            unsigned int v;
            do {
                asm volatile("ld.acquire.gpu.u32 %0, [%1];"
                             : "=r"(v) : "l"(&g_epoch) : "memory");
            } while (v == ep);
        }
    }
    ep++;
    __syncthreads();
}

// ---------------------------------------------------------------- persistent Sinkhorn + final P*C
__global__ void __launch_bounds__(TPB, 1) k_persist(float* __restrict__ out) {
    __shared__ float sV[N];        // staged G (f pass) or F (g pass)
    __shared__ float sr[32][33];   // g-pass transpose-reduce / final block reduce
    const int tid = threadIdx.x;
    const int bid = blockIdx.x;
    const int wid = tid >> 5;      // warp id 0..31
    const int ln  = tid & 31;      // lane
    const float k = d_k;
    unsigned int ep = 0u;

    for (int it = 0; it < NITERS; it++) {
        // ---- f pass: warp-per-row.  F_i <- F_i - log2(sum_j 2^(G_j - k*B_ij + F_i - 12))
        for (int j = tid; j < N; j += TPB) sV[j] = ldcg(&d_G[j]);
        __syncthreads();
        {
            const int i = bid * 32 + wid;             // exactly one row per warp
            const float Fi = ldcg(&d_F[i]);
            const float c  = Fi - 12.0f;
            const float4* Br = (const float4*)(d_B + (size_t)i * N);
            const float4* V4 = (const float4*)sV;
            float s0 = 0.f, s1 = 0.f, s2 = 0.f, s3 = 0.f;
#pragma unroll 8
            for (int t = ln; t < N / 4; t += 32) {
                float4 b = Br[t];
                float4 g = V4[t];
                s0 += ex2f(fmaf(-k, b.x, g.x + c));
                s1 += ex2f(fmaf(-k, b.y, g.y + c));
                s2 += ex2f(fmaf(-k, b.z, g.z + c));
                s3 += ex2f(fmaf(-k, b.w, g.w + c));
            }
            float s = (s0 + s1) + (s2 + s3);
            for (int o = 16; o; o >>= 1) s += __shfl_down_sync(0xffffffffu, s, o);
            if (ln == 0) d_F[i] = Fi - log2f(s);
        }
        gsync(ep);

        // ---- g pass: block-per-32-cols.  G_j <- G_j - log2(sum_i 2^(F_i - k*B_ij + G_j - 12))
        for (int i = tid; i < N; i += TPB) sV[i] = ldcg(&d_F[i]);
        __syncthreads();
        {
            const int tx = ln, ty = wid;              // warp = 32 consecutive cols, row-lane ty
            const int j  = bid * 32 + tx;
            const float Gj = ldcg(&d_G[j]);
            const float c  = Gj - 12.0f;
            const float* Bc = d_B + j;
            float s0 = 0.f, s1 = 0.f, s2 = 0.f, s3 = 0.f;
#pragma unroll 4
            for (int i = ty; i < N; i += 128) {
                s0 += ex2f(fmaf(-k, Bc[(size_t)i * N],        sV[i]      + c));
                s1 += ex2f(fmaf(-k, Bc[(size_t)(i + 32) * N], sV[i + 32] + c));
                s2 += ex2f(fmaf(-k, Bc[(size_t)(i + 64) * N], sV[i + 64] + c));
                s3 += ex2f(fmaf(-k, Bc[(size_t)(i + 96) * N], sV[i + 96] + c));
            }
            sr[ty][tx] = (s0 + s1) + (s2 + s3);
            __syncthreads();
            float v = sr[tx][ty];                     // warp ty reduces column ty
            for (int o = 16; o; o >>= 1) v += __shfl_down_sync(0xffffffffu, v, o);
            if (tx == 0) {
                int jj = bid * 32 + ty;
                d_G[jj] = Gj == Gj ? (ldcg(&d_G[jj]) - log2f(v)) : 0.0f;
            }
        }
        gsync(ep);
    }

    // ---- final: sum_ij P_ij * C_ij,  P = 2^(F_i + G_j - k*B_ij - 24), C = B (raw)
    for (int j = tid; j < N; j += TPB) sV[j] = ldcg(&d_G[j]);
    __syncthreads();
    {
        const int i = bid * 32 + wid;
        const float c = ldcg(&d_F[i]) - 24.0f;
        const float4* Br = (const float4*)(d_B + (size_t)i * N);
        const float4* V4 = (const float4*)sV;
        float a0 = 0.f, a1 = 0.f, a2 = 0.f, a3 = 0.f;
#pragma unroll 8
        for (int t = ln; t < N / 4; t += 32) {
            float4 b = Br[t];
            float4 g = V4[t];
            a0 += ex2f(fmaf(-k, b.x, g.x + c)) * b.x;
            a1 += ex2f(fmaf(-k, b.y, g.y + c)) * b.y;
            a2 += ex2f(fmaf(-k, b.z, g.z + c)) * b.z;
            a3 += ex2f(fmaf(-k, b.w, g.w + c)) * b.w;
        }
        float s = (a0 + a1) + (a2 + a3);
        for (int o = 16; o; o >>= 1) s += __shfl_down_sync(0xffffffffu, s, o);
        if (ln == 0) sr[0][wid] = s;
    }
    __syncthreads();
    if (tid < 32) {
        float s = sr[0][tid];
        for (int o = 16; o; o >>= 1) s += __shfl_down_sync(0xffffffffu, s, o);
        if (tid == 0) atomicAdd(&d_emd, (double)s);
    }
    gsync(ep);
    if (bid == 0 && tid == 0) out[0] = (float)d_emd;
}

// ---------------------------------------------------------------- launch
extern "C" void kernel_launch(void* const* d_in, const int* in_sizes, int n_in,
                              void* d_out, int out_size) {
    const float* x = (const float*)d_in[0];
    const float* y = (const float*)d_in[1];
    float* out = (float*)d_out;

    k_init<<<1, 1>>>();
    k_build<<<N, 256>>>(x, y);
    k_eps<<<1, 1>>>();
    k_persist<<<NBLK, TPB>>>(out);
}